// round 2
// baseline (speedup 1.0000x reference)
#include <cuda_runtime.h>
#include <cuda_bf16.h>
#include <utility>
#include <cstddef>

// ---------------------------------------------------------------------------
// Compile-time reproduction of the reference codebook.
//
// reference: np.random.RandomState(0).choice([1.0f,3.0f], size=(512,8))
// Legacy RandomState.randint(0, 2, dtype=int64) path: masked 32-bit MT19937
// draws, idx[k] = tempered_next32() & 1. Grid row r, element j uses draw
// k = r*8 + j; value = 1 + 2*idx. Only the PATTERN (8-bit mask of which
// elements are 3) matters: duplicates dequantize identically.
// (Confirmed by R1 bench: rel_err 6.2e-8.)
// ---------------------------------------------------------------------------

struct Tables { bool present[256]; };

__host__ __device__ constexpr unsigned mt_temper(unsigned y) {
    y ^= (y >> 11);
    y ^= (y << 7)  & 0x9d2c5680u;
    y ^= (y << 15) & 0xefc60000u;
    y ^= (y >> 18);
    return y;
}

__host__ __device__ constexpr Tables make_tables() {
    unsigned mt[624] = {};
    {
        unsigned s = 0u;  // seed = 0
        for (int i = 0; i < 624; ++i) {
            mt[i] = s;
            s = 1812433253u * (s ^ (s >> 30)) + (unsigned)(i + 1);
        }
    }
    int pos = 624;
    Tables t{};
    for (int i = 0; i < 256; ++i) t.present[i] = false;
    for (int r = 0; r < 512; ++r) {
        unsigned p = 0;
        for (int j = 0; j < 8; ++j) {
            if (pos == 624) {
                for (int i = 0; i < 624; ++i) {
                    unsigned y = (mt[i] & 0x80000000u) | (mt[(i + 1) % 624] & 0x7fffffffu);
                    mt[i] = mt[(i + 397) % 624] ^ (y >> 1) ^ ((y & 1u) ? 0x9908b0dfu : 0u);
                }
                pos = 0;
            }
            unsigned bit = mt_temper(mt[pos++]) & 1u;
            p |= bit << j;
        }
        t.present[p] = true;
    }
    return t;
}

constexpr Tables TBL = make_tables();

__host__ __device__ constexpr int popc8(int p) {
    int k = 0;
    for (int j = 0; j < 8; ++j) k += (p >> j) & 1;
    return k;
}

// ---------------------------------------------------------------------------
// Per-thread state (compile-time indexed -> registers)
// ---------------------------------------------------------------------------
struct St {
    float ulo[16];   // ulo[l] = S + 2*T_lo(l)   (fmaf, single rounding)
    float th2[16];   // th2[h] = 2*T_hi(h)       (exact *2)
    float gmax[9];   // per-popcount-group max of u = dot(a, q)
};

// ---- Phase 1: pure-FMNMX group maxes (no index tracking) -------------------
template <int P>
__device__ __forceinline__ void step(St& s) {
    if constexpr (TBL.present[P]) {
        constexpr int K = popc8(P);
        constexpr int L = P & 15;
        constexpr int H = P >> 4;
        float u;
        if constexpr (H == 0) u = s.ulo[L];
        else                  u = s.ulo[L] + s.th2[H];
        s.gmax[K] = fmaxf(s.gmax[K], u);   // FMNMX, 1 alu op
    }
}

template <size_t... Ps>
__device__ __forceinline__ void run_all(St& s, std::index_sequence<Ps...>) {
    (step<(int)Ps>(s), ...);
}

// ---- Phase 3: recover winning pattern for known popcount group -------------
// Scan DESCENDING P, overwrite on exact match -> ends at smallest matching P,
// i.e. identical "first wins" semantics (and bit-identical output) to the
// R1 kernel's strict-> tracking loop.
template <int K, int P>
__device__ __forceinline__ void rec_step(const St& s, float bestU, int& bp) {
    if constexpr (TBL.present[P] && popc8(P) == K) {
        constexpr int L = P & 15;
        constexpr int H = P >> 4;
        float u;
        if constexpr (H == 0) u = s.ulo[L];
        else                  u = s.ulo[L] + s.th2[H];   // same expr -> same rounding as phase 1
        if (u == bestU) bp = P;
    }
}

template <int K, size_t... Qs>
__device__ __forceinline__ void rec_all(const St& s, float bestU, int& bp,
                                        std::index_sequence<Qs...>) {
    (rec_step<K, 255 - (int)Qs>(s, bestU, bp), ...);
}

template <int K>
__device__ __forceinline__ int recover(const St& s, float bestU) {
    int bp = 0;
    rec_all<K>(s, bestU, bp, std::make_index_sequence<256>{});
    return bp;
}

// ---------------------------------------------------------------------------
// Main kernel: one thread per 8-element block.
// ---------------------------------------------------------------------------
__global__ void __launch_bounds__(256)
iq2xs_kernel(const float* __restrict__ w, float* __restrict__ out, int nb) {
    int b = blockIdx.x * 256 + threadIdx.x;
    if (b >= nb) return;

    const float4* w4 = reinterpret_cast<const float4*>(w) + 2 * (size_t)b;
    float4 v0 = w4[0];
    float4 v1 = w4[1];
    float wv[8] = {v0.x, v0.y, v0.z, v0.w, v1.x, v1.y, v1.z, v1.w};

    float a[8];
#pragma unroll
    for (int i = 0; i < 8; ++i) a[i] = fabsf(wv[i]);

    // Subset-sum DP over low half (0..3) and high half (4..7).
    float tlo[16], thi[16];
    tlo[0] = 0.f;
    tlo[1] = a[0];
    tlo[2] = a[1];
    tlo[3] = tlo[1] + a[1];
    tlo[4] = a[2];
    tlo[5] = tlo[1] + a[2];
    tlo[6] = tlo[2] + a[2];
    tlo[7] = tlo[3] + a[2];
#pragma unroll
    for (int m = 0; m < 8; ++m) tlo[8 + m] = tlo[m] + a[3];

    thi[0] = 0.f;
    thi[1] = a[4];
    thi[2] = a[5];
    thi[3] = thi[1] + a[5];
    thi[4] = a[6];
    thi[5] = thi[1] + a[6];
    thi[6] = thi[2] + a[6];
    thi[7] = thi[3] + a[6];
#pragma unroll
    for (int m = 0; m < 8; ++m) thi[8 + m] = thi[m] + a[7];

    float S = tlo[15] + thi[15];   // sum of all |w| in block

    St s;
#pragma unroll
    for (int l = 0; l < 16; ++l) s.ulo[l] = fmaf(2.f, tlo[l], S);
#pragma unroll
    for (int h = 0; h < 16; ++h) s.th2[h] = 2.f * thi[h];
#pragma unroll
    for (int k = 0; k < 9; ++k) s.gmax[k] = -1.f;

    // Phase 1: fully unrolled FMNMX scan over present patterns.
    run_all(s, std::make_index_sequence<256>{});

    // Phase 2: cross-group resolution. score = u^2 / (8 + 8k); empty groups
    // carry gmax = -1 -> sc < 0 and never beat a real group (u >= 0).
    float bestSc = -1e30f, bestU = 0.f, bestNorm = 8.f;
    int bestK = 0;
#pragma unroll
    for (int k = 0; k < 9; ++k) {
        float g = s.gmax[k];
        float sc = g * fabsf(g) * (1.f / (8.f + 8.f * (float)k));
        if (sc > bestSc) {
            bestSc = sc;
            bestU = g;
            bestK = k;
            bestNorm = 8.f + 8.f * (float)k;
        }
    }

    // Phase 3: recover the winning pattern, only for the winning group.
    int bestP;
    switch (bestK) {
        case 0: bestP = recover<0>(s, bestU); break;
        case 1: bestP = recover<1>(s, bestU); break;
        case 2: bestP = recover<2>(s, bestU); break;
        case 3: bestP = recover<3>(s, bestU); break;
        case 4: bestP = recover<4>(s, bestU); break;
        case 5: bestP = recover<5>(s, bestU); break;
        case 6: bestP = recover<6>(s, bestU); break;
        case 7: bestP = recover<7>(s, bestU); break;
        default: bestP = recover<8>(s, bestU); break;
    }

    // Least-squares scale for the winning codeword (division, like reference)
    float scale = bestU / bestNorm;
    float s3 = 3.f * scale;

    float o[8];
#pragma unroll
    for (int i = 0; i < 8; ++i) {
        float m = ((bestP >> i) & 1) ? s3 : scale;
        // sign(w)=0 at w==+-0 -> deq 0 in the reference
        float deq = (wv[i] == 0.f) ? 0.f : copysignf(m, wv[i]);
        // STE as computed by the reference: w + (deq - w), same rounding order
        o[i] = wv[i] + (deq - wv[i]);
    }

    float4 r0 = {o[0], o[1], o[2], o[3]};
    float4 r1 = {o[4], o[5], o[6], o[7]};
    float4* out4 = reinterpret_cast<float4*>(out) + 2 * (size_t)b;
    out4[0] = r0;
    out4[1] = r1;
}

extern "C" void kernel_launch(void* const* d_in, const int* in_sizes, int n_in,
                              void* d_out, int out_size) {
    const float* w = (const float*)d_in[0];
    float* out = (float*)d_out;
    int n = in_sizes[0];
    int nb = n / 8;
    int threads = 256;
    int blocks = (nb + threads - 1) / threads;
    iq2xs_kernel<<<blocks, threads>>>(w, out, nb);
}

// round 3
// speedup vs baseline: 1.3034x; 1.3034x over previous
#include <cuda_runtime.h>
#include <cuda_bf16.h>
#include <utility>
#include <cstddef>

// ---------------------------------------------------------------------------
// Compile-time reproduction of the reference codebook.
//
// reference: np.random.RandomState(0).choice([1.0f,3.0f], size=(512,8))
// Legacy RandomState.randint(0, 2, dtype=int64) path: masked 32-bit MT19937
// draws, idx[k] = tempered_next32() & 1. Grid row r, element j uses draw
// k = r*8 + j; value = 1 + 2*idx. Only the PATTERN (8-bit mask of which
// elements are 3) matters: duplicates dequantize identically.
// (Confirmed: R1 bench rel_err 6.2e-8.)
// ---------------------------------------------------------------------------

struct Tables { bool present[256]; };

__host__ __device__ constexpr unsigned mt_temper(unsigned y) {
    y ^= (y >> 11);
    y ^= (y << 7)  & 0x9d2c5680u;
    y ^= (y << 15) & 0xefc60000u;
    y ^= (y >> 18);
    return y;
}

__host__ __device__ constexpr Tables make_tables() {
    unsigned mt[624] = {};
    {
        unsigned s = 0u;  // seed = 0
        for (int i = 0; i < 624; ++i) {
            mt[i] = s;
            s = 1812433253u * (s ^ (s >> 30)) + (unsigned)(i + 1);
        }
    }
    int pos = 624;
    Tables t{};
    for (int i = 0; i < 256; ++i) t.present[i] = false;
    for (int r = 0; r < 512; ++r) {
        unsigned p = 0;
        for (int j = 0; j < 8; ++j) {
            if (pos == 624) {
                for (int i = 0; i < 624; ++i) {
                    unsigned y = (mt[i] & 0x80000000u) | (mt[(i + 1) % 624] & 0x7fffffffu);
                    mt[i] = mt[(i + 397) % 624] ^ (y >> 1) ^ ((y & 1u) ? 0x9908b0dfu : 0u);
                }
                pos = 0;
            }
            unsigned bit = mt_temper(mt[pos++]) & 1u;
            p |= bit << j;
        }
        t.present[p] = true;
    }
    return t;
}

constexpr Tables TBL = make_tables();

__host__ __device__ constexpr int popc8(int p) {
    int k = 0;
    for (int j = 0; j < 8; ++j) k += (p >> j) & 1;
    return k;
}

// ---------------------------------------------------------------------------
// Per-thread state (compile-time indexed -> registers)
// ---------------------------------------------------------------------------
struct St {
    float ulo[16];   // ulo[l] = S + 2*T_lo(l)   (fmaf, single rounding)
    float th2[16];   // th2[h] = 2*T_hi(h)       (exact *2)
    float gmax[9];   // per-popcount-group max of u = dot(a, q)
    int   gidx[9];   // pattern achieving the group max (first/smallest P wins)
};

template <int P>
__device__ __forceinline__ void step(St& s) {
    if constexpr (TBL.present[P]) {
        constexpr int K = popc8(P);
        constexpr int L = P & 15;
        constexpr int H = P >> 4;
        float u;
        if constexpr (H == 0) u = s.ulo[L];
        else                  u = s.ulo[L] + s.th2[H];
        if (u > s.gmax[K]) { s.gmax[K] = u; s.gidx[K] = P; }
    }
}

template <size_t... Ps>
__device__ __forceinline__ void run_all(St& s, std::index_sequence<Ps...>) {
    (step<(int)Ps>(s), ...);
}

// ---------------------------------------------------------------------------
// Main kernel: one thread per 8-element block.
// __launch_bounds__(256, 6): cap regs at 40 -> 6 CTAs/SM (75% occ target).
// ---------------------------------------------------------------------------
__global__ void __launch_bounds__(256, 6)
iq2xs_kernel(const float* __restrict__ w, float* __restrict__ out, int nb) {
    int b = blockIdx.x * 256 + threadIdx.x;
    if (b >= nb) return;

    const float4* w4 = reinterpret_cast<const float4*>(w) + 2 * (size_t)b;
    float4 v0 = w4[0];
    float4 v1 = w4[1];

    // Magnitudes only; w values are reloaded (L1-resident) after the argmax
    // so they don't occupy registers across the 221-pattern scan.
    float a[8] = {fabsf(v0.x), fabsf(v0.y), fabsf(v0.z), fabsf(v0.w),
                  fabsf(v1.x), fabsf(v1.y), fabsf(v1.z), fabsf(v1.w)};

    // Subset-sum DP over low half (0..3) and high half (4..7).
    float tlo[16], thi[16];
    tlo[0] = 0.f;
    tlo[1] = a[0];
    tlo[2] = a[1];
    tlo[3] = tlo[1] + a[1];
    tlo[4] = a[2];
    tlo[5] = tlo[1] + a[2];
    tlo[6] = tlo[2] + a[2];
    tlo[7] = tlo[3] + a[2];
#pragma unroll
    for (int m = 0; m < 8; ++m) tlo[8 + m] = tlo[m] + a[3];

    thi[0] = 0.f;
    thi[1] = a[4];
    thi[2] = a[5];
    thi[3] = thi[1] + a[5];
    thi[4] = a[6];
    thi[5] = thi[1] + a[6];
    thi[6] = thi[2] + a[6];
    thi[7] = thi[3] + a[6];
#pragma unroll
    for (int m = 0; m < 8; ++m) thi[8 + m] = thi[m] + a[7];

    float S = tlo[15] + thi[15];   // sum of all |w| in block

    St s;
#pragma unroll
    for (int l = 0; l < 16; ++l) s.ulo[l] = fmaf(2.f, tlo[l], S);
#pragma unroll
    for (int h = 0; h < 16; ++h) s.th2[h] = 2.f * thi[h];
#pragma unroll
    for (int k = 0; k < 9; ++k) { s.gmax[k] = -1.f; s.gidx[k] = 0; }

    // Phase 1: fully unrolled scan over present patterns, grouped by popcount
    // so the norm divide stays out of the inner loop; comparisons exact fp32.
    run_all(s, std::make_index_sequence<256>{});

    // Phase 2: cross-group resolution. score = u^2 / (8 + 8k). Empty groups
    // carry gmax = -1 -> sc < 0, never beats a real group (u >= 0 -> sc >= 0).
    float bestSc = -1e30f, bestU = 0.f, bestNorm = 8.f;
    int bestP = 0;
#pragma unroll
    for (int k = 0; k < 9; ++k) {
        float g = s.gmax[k];
        float sc = g * fabsf(g) * (1.f / (8.f + 8.f * (float)k));
        if (sc > bestSc) {
            bestSc = sc;
            bestU = g;
            bestP = s.gidx[k];
            bestNorm = 8.f + 8.f * (float)k;
        }
    }

    // Least-squares scale for the winning codeword (division, like reference)
    float scale = bestU / bestNorm;
    float s3 = 3.f * scale;

    // Reload w (L1 hit) and emit STE output: w + (deq - w), same rounding
    // order as the reference. sign(w)=0 at +-0 -> deq 0.
    v0 = w4[0];
    v1 = w4[1];
    float wv[8] = {v0.x, v0.y, v0.z, v0.w, v1.x, v1.y, v1.z, v1.w};

    float o[8];
#pragma unroll
    for (int i = 0; i < 8; ++i) {
        float m = ((bestP >> i) & 1) ? s3 : scale;
        float deq = (wv[i] == 0.f) ? 0.f : copysignf(m, wv[i]);
        o[i] = wv[i] + (deq - wv[i]);
    }

    float4 r0 = {o[0], o[1], o[2], o[3]};
    float4 r1 = {o[4], o[5], o[6], o[7]};
    float4* out4 = reinterpret_cast<float4*>(out) + 2 * (size_t)b;
    out4[0] = r0;
    out4[1] = r1;
}

extern "C" void kernel_launch(void* const* d_in, const int* in_sizes, int n_in,
                              void* d_out, int out_size) {
    const float* w = (const float*)d_in[0];
    float* out = (float*)d_out;
    int n = in_sizes[0];
    int nb = n / 8;
    int threads = 256;
    int blocks = (nb + threads - 1) / threads;
    iq2xs_kernel<<<blocks, threads>>>(w, out, nb);
}

// round 4
// speedup vs baseline: 1.8680x; 1.4332x over previous
#include <cuda_runtime.h>
#include <cuda_bf16.h>
#include <utility>
#include <cstddef>

// ---------------------------------------------------------------------------
// Compile-time reproduction of the reference codebook.
// reference: np.random.RandomState(0).choice([1.0f,3.0f], size=(512,8))
// Legacy randint path: masked 32-bit MT19937 draws, bit = tempered() & 1.
// Only the 8-bit PATTERN (which elements are 3) matters; duplicates in the
// 512-row table dequantize identically. (Confirmed: R1 rel_err 6.2e-8.)
// ---------------------------------------------------------------------------

struct Tables { bool present[256]; };

__host__ __device__ constexpr unsigned mt_temper(unsigned y) {
    y ^= (y >> 11);
    y ^= (y << 7)  & 0x9d2c5680u;
    y ^= (y << 15) & 0xefc60000u;
    y ^= (y >> 18);
    return y;
}

__host__ __device__ constexpr Tables make_tables() {
    unsigned mt[624] = {};
    {
        unsigned s = 0u;  // seed = 0
        for (int i = 0; i < 624; ++i) {
            mt[i] = s;
            s = 1812433253u * (s ^ (s >> 30)) + (unsigned)(i + 1);
        }
    }
    int pos = 624;
    Tables t{};
    for (int i = 0; i < 256; ++i) t.present[i] = false;
    for (int r = 0; r < 512; ++r) {
        unsigned p = 0;
        for (int j = 0; j < 8; ++j) {
            if (pos == 624) {
                for (int i = 0; i < 624; ++i) {
                    unsigned y = (mt[i] & 0x80000000u) | (mt[(i + 1) % 624] & 0x7fffffffu);
                    mt[i] = mt[(i + 397) % 624] ^ (y >> 1) ^ ((y & 1u) ? 0x9908b0dfu : 0u);
                }
                pos = 0;
            }
            unsigned bit = mt_temper(mt[pos++]) & 1u;
            p |= bit << j;
        }
        t.present[p] = true;
    }
    return t;
}

constexpr Tables TBL = make_tables();

__host__ __device__ constexpr int popc8(int p) {
    int k = 0;
    for (int j = 0; j < 8; ++j) k += (p >> j) & 1;
    return k;
}

// ---------------------------------------------------------------------------
// Compile-time quad table: present patterns grouped by popcount, packed into
// quads of <=4 (ascending P within group; partial quads pad by replicating
// the last pattern -- duplicates are harmless for max/resolve).
// ---------------------------------------------------------------------------
struct QuadTab {
    int n;
    int p[80][4];
    int k[80];
    int cnt[80];
};

__host__ __device__ constexpr QuadTab make_quads() {
    QuadTab q{};
    q.n = 0;
    for (int kk = 0; kk <= 8; ++kk) {
        int buf[80] = {};
        int m = 0;
        for (int P = 0; P < 256; ++P)
            if (TBL.present[P] && popc8(P) == kk) buf[m++] = P;
        for (int i = 0; i < m; i += 4) {
            int c = (m - i < 4) ? (m - i) : 4;
            for (int j = 0; j < 4; ++j)
                q.p[q.n][j] = buf[i + (j < c ? j : c - 1)];
            q.k[q.n] = kk;
            q.cnt[q.n] = c;
            q.n++;
        }
    }
    return q;
}

constexpr QuadTab QT = make_quads();

// ---------------------------------------------------------------------------
// Per-thread scan state (compile-time indexed -> registers)
// ---------------------------------------------------------------------------
struct St {
    float ulo[16];      // ulo[l] = S + 2*T_lo(l)  (fmaf, single rounding)
    float th2[16];      // th2[h] = 2*T_hi(h)      (exact *2)
    float gmax[9];      // per-popcount-group max of u = dot(a, q)
    unsigned qid[9];    // packed 4-byte quad achieving the group max
};

template <int P>
__device__ __forceinline__ float val(const St& s) {
    constexpr int L = P & 15;
    constexpr int H = P >> 4;
    if constexpr (H == 0) return s.ulo[L];
    else                  return s.ulo[L] + s.th2[H];
}

template <int I>
__device__ __forceinline__ void qstep(St& s) {
    if constexpr (I < QT.n) {
        constexpr int K = QT.k[I];
        constexpr int c = QT.cnt[I];
        constexpr unsigned qid =
            (unsigned)QT.p[I][0] | ((unsigned)QT.p[I][1] << 8) |
            ((unsigned)QT.p[I][2] << 16) | ((unsigned)QT.p[I][3] << 24);
        float m = val<QT.p[I][0]>(s);
        if constexpr (c > 1) m = fmaxf(m, val<QT.p[I][1]>(s));
        if constexpr (c > 2) m = fmaxf(m, val<QT.p[I][2]>(s));
        if constexpr (c > 3) m = fmaxf(m, val<QT.p[I][3]>(s));
        if (m > s.gmax[K]) { s.gmax[K] = m; s.qid[K] = qid; }
    }
}

template <size_t... Is>
__device__ __forceinline__ void run_all(St& s, std::index_sequence<Is...>) {
    (qstep<(int)Is>(s), ...);
}

// ---------------------------------------------------------------------------
// Main kernel: one thread per 8-element block.
// ---------------------------------------------------------------------------
__global__ void __launch_bounds__(256)
iq2xs_kernel(const float* __restrict__ w, float* __restrict__ out, int nb) {
    int b = blockIdx.x * 256 + threadIdx.x;
    if (b >= nb) return;

    const float4* w4 = reinterpret_cast<const float4*>(w) + 2 * (size_t)b;
    float4 v0 = w4[0];
    float4 v1 = w4[1];

    // Magnitudes (w reloaded from L1 after the scan; keeps live range small)
    float a[8] = {fabsf(v0.x), fabsf(v0.y), fabsf(v0.z), fabsf(v0.w),
                  fabsf(v1.x), fabsf(v1.y), fabsf(v1.z), fabsf(v1.w)};

    // Subset-sum DP over low half (0..3) and high half (4..7).
    float tlo[16], thi[16];
    tlo[0] = 0.f;
    tlo[1] = a[0];
    tlo[2] = a[1];
    tlo[3] = tlo[1] + a[1];
    tlo[4] = a[2];
    tlo[5] = tlo[1] + a[2];
    tlo[6] = tlo[2] + a[2];
    tlo[7] = tlo[3] + a[2];
#pragma unroll
    for (int m = 0; m < 8; ++m) tlo[8 + m] = tlo[m] + a[3];

    thi[0] = 0.f;
    thi[1] = a[4];
    thi[2] = a[5];
    thi[3] = thi[1] + a[5];
    thi[4] = a[6];
    thi[5] = thi[1] + a[6];
    thi[6] = thi[2] + a[6];
    thi[7] = thi[3] + a[6];
#pragma unroll
    for (int m = 0; m < 8; ++m) thi[8 + m] = thi[m] + a[7];

    float S = tlo[15] + thi[15];   // sum of all |w| in block

    St s;
#pragma unroll
    for (int l = 0; l < 16; ++l) s.ulo[l] = fmaf(2.f, tlo[l], S);
#pragma unroll
    for (int h = 0; h < 16; ++h) s.th2[h] = 2.f * thi[h];
#pragma unroll
    for (int k = 0; k < 9; ++k) { s.gmax[k] = -1.f; s.qid[k] = 0u; }

    // Phase 1: fully unrolled quad-tournament scan (1.5 alu ops / pattern).
    run_all(s, std::make_index_sequence<80>{});

    // Phase 2: cross-group resolution. score = u^2 / (8+8k); empty groups
    // carry gmax = -1 -> sc < 0 and never beat a real group (u >= 0).
    float bestSc = -1e30f, bestNorm = 8.f;
    unsigned bestQ = 0u;
#pragma unroll
    for (int k = 0; k < 9; ++k) {
        float g = s.gmax[k];
        float sc = g * fabsf(g) * (1.f / (8.f + 8.f * (float)k));
        if (sc > bestSc) {
            bestSc = sc;
            bestQ = s.qid[k];
            bestNorm = 8.f + 8.f * (float)k;
        }
    }

    // Reload w (L1 hit) for resolve + epilogue.
    v0 = w4[0];
    v1 = w4[1];
    float wv[8] = {v0.x, v0.y, v0.z, v0.w, v1.x, v1.y, v1.z, v1.w};

    // Phase 3: resolve within the winning quad (branchless, once per thread).
    // Ascending byte order + strict '>' keeps first-wins semantics; padded
    // duplicate bytes tie and are skipped by strict '>'.
    float bestU = -1.f;
    int bestP = 0;
#pragma unroll
    for (int j = 0; j < 4; ++j) {
        int P = (int)((bestQ >> (8 * j)) & 255u);
        float t = 0.f;
#pragma unroll
        for (int i = 0; i < 8; ++i)
            if (P & (1 << i)) t += fabsf(wv[i]);
        float u = fmaf(2.f, t, S);
        if (u > bestU) { bestU = u; bestP = P; }
    }

    // Least-squares scale for the winning codeword.
    float scale = bestU / bestNorm;
    float s3 = 3.f * scale;

    // STE output: w + (deq - w), reference rounding order. sign(+-0)=0 -> deq 0.
    float o[8];
#pragma unroll
    for (int i = 0; i < 8; ++i) {
        float m = ((bestP >> i) & 1) ? s3 : scale;
        float deq = (wv[i] == 0.f) ? 0.f : copysignf(m, wv[i]);
        o[i] = wv[i] + (deq - wv[i]);
    }

    float4 r0 = {o[0], o[1], o[2], o[3]};
    float4 r1 = {o[4], o[5], o[6], o[7]};
    float4* out4 = reinterpret_cast<float4*>(out) + 2 * (size_t)b;
    out4[0] = r0;
    out4[1] = r1;
}

extern "C" void kernel_launch(void* const* d_in, const int* in_sizes, int n_in,
                              void* d_out, int out_size) {
    const float* w = (const float*)d_in[0];
    float* out = (float*)d_out;
    int n = in_sizes[0];
    int nb = n / 8;
    int threads = 256;
    int blocks = (nb + threads - 1) / threads;
    iq2xs_kernel<<<blocks, threads>>>(w, out, nb);
}